// round 2
// baseline (speedup 1.0000x reference)
#include <cuda_runtime.h>
#include <math.h>

#define BSZ 2
#define NP  2048
#define CH  256
#define FFNC 1024
#define NROW (BSZ*NP)

// ---------------- scratch (device globals; no allocations) ----------------
__device__ float g_Q[(size_t)BSZ*NP*NP];     // IPOT transport matrix, updated in place
__device__ float g_G[(size_t)BSZ*NP*NP];     // exp(-cost/10)
__device__ float g_Xtp[(size_t)BSZ*NP*CH];   // pts feat transposed [b,n,c]
__device__ float g_Xti[(size_t)BSZ*NP*CH];   // img feat transposed [b,n,c]
__device__ float g_imf[(size_t)BSZ*CH*NP];   // img projected feat [b,c,m]
__device__ float g_xcat[(size_t)BSZ*NP*2*CH];// [pf ; img_att] token-major [b,n,512]
__device__ float g_x[(size_t)BSZ*NP*CH];     // post out-proj (+LN in place)
__device__ float g_h[(size_t)BSZ*NP*FFNC];   // FFN hidden
__device__ float g_y2[(size_t)BSZ*NP*CH];    // FFN out + residual
__device__ float g_pcls[NROW], g_icls[NROW];
__device__ float g_av[NROW], g_bv[NROW], g_wv[NROW];

// ---------------- helpers ----------------
__device__ __forceinline__ float blockSum256(float v) {
    #pragma unroll
    for (int o = 16; o; o >>= 1) v += __shfl_xor_sync(0xffffffffu, v, o);
    __shared__ float sh[8];
    int w = threadIdx.x >> 5;
    if ((threadIdx.x & 31) == 0) sh[w] = v;
    __syncthreads();
    if (threadIdx.x < 8) {
        v = sh[threadIdx.x];
        #pragma unroll
        for (int o = 4; o; o >>= 1) v += __shfl_xor_sync(0xffu, v, o);
    }
    return v;  // valid in thread 0
}

// ---------------- transpose [b,C,N] -> [b,N,C] ----------------
__global__ void k_transpose(const float* __restrict__ src, int which) {
    __shared__ float t[32][33];
    int b = blockIdx.z;
    float* dst = which ? g_Xti : g_Xtp;
    const float* s = src + (size_t)b * CH * NP;
    float* d = dst + (size_t)b * NP * CH;
    int n0 = blockIdx.x * 32, c0 = blockIdx.y * 32;
    for (int i = threadIdx.y; i < 32; i += 8)
        t[i][threadIdx.x] = s[(size_t)(c0 + i) * NP + n0 + threadIdx.x];
    __syncthreads();
    for (int i = threadIdx.y; i < 32; i += 8)
        d[(size_t)(n0 + i) * CH + c0 + threadIdx.x] = t[threadIdx.x][i];
}

// ---------------- pcls/icls = max over classes of sigmoid ----------------
__global__ void k_cls(const float* __restrict__ pc, const float* __restrict__ ic) {
    int idx = blockIdx.x * 256 + threadIdx.x;   // 0..4095
    int b = idx >> 11, n = idx & (NP - 1);
    const float* p = pc + (size_t)b * 10 * NP + n;
    const float* q = ic + (size_t)b * 10 * NP + n;
    float mp = -1e30f, mi = -1e30f;
    #pragma unroll
    for (int c = 0; c < 10; c++) {
        mp = fmaxf(mp, p[(size_t)c * NP]);
        mi = fmaxf(mi, q[(size_t)c * NP]);
    }
    g_pcls[idx] = 1.f / (1.f + expf(-mp));
    g_icls[idx] = 1.f / (1.f + expf(-mi));
}

// ---------------- G = exp(-cost/10) ----------------
__global__ void k_cost(const float* __restrict__ ppos, const float* __restrict__ ipos) {
    int n = blockIdx.x, b = blockIdx.y;
    float2 pp = ((const float2*)ppos)[b * NP + n];
    const float2* ip = (const float2*)ipos + (size_t)b * NP;
    float* grow = g_G + ((size_t)(b * NP + n)) * NP;
    for (int m = threadIdx.x; m < NP; m += 256) {
        float2 q = ip[m];
        float dx = pp.x - q.x, dy = pp.y - q.y;
        grow[m] = expf(-0.1f * sqrtf(dx * dx + dy * dy));
    }
}

__global__ void k_binit() {
    int i = blockIdx.x * 256 + threadIdx.x;
    if (i < NROW) g_bv[i] = 1.0f / NP;
}

// ---------------- IPOT row pass: Q in place, compute a ----------------
__global__ void k_ipot_row(int t) {
    int n = blockIdx.x, b = blockIdx.y;
    int row = b * NP + n;
    float4* qrow = (float4*)(g_Q + (size_t)row * NP);
    const float4* grow = (const float4*)(g_G + (size_t)row * NP);
    const float4* bv = (const float4*)(g_bv + b * NP);
    float ap = (t > 1) ? g_av[row] : 1.0f;
    float u = 0.f;
    #pragma unroll
    for (int j = 0; j < 2; j++) {
        int i = threadIdx.x + j * 256;
        float4 g4 = grow[i];
        float4 b4 = bv[i];
        float4 q4;
        if (t == 1) {
            q4.x = fmaxf(g4.x, 1e-6f); q4.y = fmaxf(g4.y, 1e-6f);
            q4.z = fmaxf(g4.z, 1e-6f); q4.w = fmaxf(g4.w, 1e-6f);
        } else {
            float4 qo = qrow[i];
            q4.x = fmaxf(g4.x * (ap * qo.x * b4.x), 1e-6f);
            q4.y = fmaxf(g4.y * (ap * qo.y * b4.y), 1e-6f);
            q4.z = fmaxf(g4.z * (ap * qo.z * b4.z), 1e-6f);
            q4.w = fmaxf(g4.w * (ap * qo.w * b4.w), 1e-6f);
        }
        qrow[i] = q4;
        u += q4.x * b4.x + q4.y * b4.y + q4.z * b4.z + q4.w * b4.w;
    }
    u = blockSum256(u);
    if (threadIdx.x == 0) g_av[row] = g_pcls[row] / (u + 1e-6f);
}

// ---------------- IPOT column pass: v = Q^T a, b = icls/(v+eps) ----------------
__global__ void k_ipot_col() {
    int b = blockIdx.y;
    int m0 = blockIdx.x * 16;
    int col = threadIdx.x & 15;
    int rg = threadIdx.x >> 4;
    const float* q = g_Q + (size_t)b * NP * NP + m0 + col;
    const float* av = g_av + b * NP;
    float v = 0.f;
    #pragma unroll 4
    for (int nn = rg; nn < NP; nn += 16)
        v += q[(size_t)nn * NP] * av[nn];
    __shared__ float s[256];
    s[threadIdx.x] = v;
    __syncthreads();
    if (threadIdx.x < 16) {
        float tot = 0.f;
        #pragma unroll
        for (int g2 = 0; g2 < 16; g2++) tot += s[g2 * 16 + threadIdx.x];
        int m = m0 + threadIdx.x;
        g_bv[b * NP + m] = g_icls[b * NP + m] / (tot + 1e-6f);
    }
}

// ---------------- w[n] = a / max(a*rowsum(Q*b), 1e-12) ----------------
__global__ void k_rownorm() {
    int n = blockIdx.x, b = blockIdx.y, row = b * NP + n;
    const float4* qrow = (const float4*)(g_Q + (size_t)row * NP);
    const float4* bv = (const float4*)(g_bv + b * NP);
    float srs = 0.f;
    #pragma unroll
    for (int j = 0; j < 2; j++) {
        int i = threadIdx.x + j * 256;
        float4 q4 = qrow[i], b4 = bv[i];
        srs += q4.x * b4.x + q4.y * b4.y + q4.z * b4.z + q4.w * b4.w;
    }
    srs = blockSum256(srs);
    if (threadIdx.x == 0) {
        float a = g_av[row];
        g_wv[row] = a / fmaxf(a * srs, 1e-12f);
    }
}

// ---------------- generic tiled GEMM: C[i,j] = sum_k A[i,k] * B[j,k] ----------------
// MODE 0: pf   A=g_Xtp[b](2048x256)   B=Wp     -> xcat[:, :256] (+bp+bqp+Wqp·ppos(i))
// MODE 1: imf  A=Wi(256x256)          B=g_Xti  -> g_imf[b,c,m]  (+bi+bkp+Wkp·ipos(j))
// MODE 2: att  A=g_Q[b]*bv[k]         B=g_imf  -> xcat[:,256:]  (*wv[i])
// MODE 3: proj A=g_xcat[b](2048x512)  B=Wout   -> g_x           (+bout)
// MODE 4: ffn1 A=g_x[b](2048x256)     B=Wf1    -> g_h           relu(+bf1)
// MODE 5: ffn2 A=g_h[b](2048x1024)    B=Wf2    -> g_y2          (+bf2 + g_x residual)
template<int MODE>
__global__ void __launch_bounds__(256) k_gemm(const float* __restrict__ e0,
                                              const float* __restrict__ p0,
                                              const float* __restrict__ p1,
                                              const float* __restrict__ p2,
                                              const float* __restrict__ p3) {
    constexpr int BM = 128, BN = 64, BK = 32;
    constexpr int K = (MODE == 0 || MODE == 1 || MODE == 4) ? 256 :
                      (MODE == 2 ? 2048 : (MODE == 3 ? 512 : 1024));
    int b = blockIdx.z;
    const float* A; const float* Bm;
    if constexpr (MODE == 0)      { A = g_Xtp + (size_t)b * NP * CH;  Bm = e0; }
    else if constexpr (MODE == 1) { A = e0;                           Bm = g_Xti + (size_t)b * NP * CH; }
    else if constexpr (MODE == 2) { A = g_Q + (size_t)b * NP * NP;    Bm = g_imf + (size_t)b * CH * NP; }
    else if constexpr (MODE == 3) { A = g_xcat + (size_t)b * NP * 2 * CH; Bm = e0; }
    else if constexpr (MODE == 4) { A = g_x + (size_t)b * NP * CH;    Bm = e0; }
    else                          { A = g_h + (size_t)b * NP * FFNC;  Bm = e0; }

    __shared__ float Asm[BK][BM + 4];
    __shared__ float Bsm[BK][BN + 4];
    int i0 = blockIdx.y * BM, j0 = blockIdx.x * BN;
    int tx = threadIdx.x & 15, ty = threadIdx.x >> 4;
    float acc[8][4];
    #pragma unroll
    for (int r = 0; r < 8; r++)
        #pragma unroll
        for (int c = 0; c < 4; c++) acc[r][c] = 0.f;

    for (int k0 = 0; k0 < K; k0 += BK) {
        #pragma unroll
        for (int s = 0; s < 4; s++) {
            int f4 = threadIdx.x + s * 256;
            int i = f4 >> 3, k4 = f4 & 7;
            float4 v = *(const float4*)(A + (size_t)(i0 + i) * K + k0 + k4 * 4);
            if constexpr (MODE == 2) {
                float4 bs = *(const float4*)(g_bv + b * NP + k0 + k4 * 4);
                v.x *= bs.x; v.y *= bs.y; v.z *= bs.z; v.w *= bs.w;
            }
            Asm[k4 * 4 + 0][i] = v.x; Asm[k4 * 4 + 1][i] = v.y;
            Asm[k4 * 4 + 2][i] = v.z; Asm[k4 * 4 + 3][i] = v.w;
        }
        #pragma unroll
        for (int s = 0; s < 2; s++) {
            int f4 = threadIdx.x + s * 256;
            int j = f4 >> 3, k4 = f4 & 7;
            float4 v = *(const float4*)(Bm + (size_t)(j0 + j) * K + k0 + k4 * 4);
            Bsm[k4 * 4 + 0][j] = v.x; Bsm[k4 * 4 + 1][j] = v.y;
            Bsm[k4 * 4 + 2][j] = v.z; Bsm[k4 * 4 + 3][j] = v.w;
        }
        __syncthreads();
        #pragma unroll
        for (int kk = 0; kk < BK; kk++) {
            float4 a0 = *(const float4*)&Asm[kk][ty * 8];
            float4 a1 = *(const float4*)&Asm[kk][ty * 8 + 4];
            float4 bb = *(const float4*)&Bsm[kk][tx * 4];
            float ar[8] = {a0.x, a0.y, a0.z, a0.w, a1.x, a1.y, a1.z, a1.w};
            float br[4] = {bb.x, bb.y, bb.z, bb.w};
            #pragma unroll
            for (int r = 0; r < 8; r++)
                #pragma unroll
                for (int c = 0; c < 4; c++) acc[r][c] += ar[r] * br[c];
        }
        __syncthreads();
    }

    #pragma unroll
    for (int r = 0; r < 8; r++) {
        int i = i0 + ty * 8 + r;
        int j = j0 + tx * 4;
        float vr[4] = {acc[r][0], acc[r][1], acc[r][2], acc[r][3]};
        if constexpr (MODE == 0) {
            float2 pp = ((const float2*)p3)[b * NP + i];
            #pragma unroll
            for (int c = 0; c < 4; c++)
                vr[c] += p0[j + c] + p1[j + c] + p2[2 * (j + c)] * pp.x + p2[2 * (j + c) + 1] * pp.y;
            *(float4*)(g_xcat + ((size_t)(b * NP + i)) * (2 * CH) + j) =
                make_float4(vr[0], vr[1], vr[2], vr[3]);
        } else if constexpr (MODE == 1) {
            float bia = p0[i] + p1[i];
            float w0 = p2[2 * i], w1 = p2[2 * i + 1];
            #pragma unroll
            for (int c = 0; c < 4; c++) {
                float2 pp = ((const float2*)p3)[b * NP + j + c];
                vr[c] += bia + w0 * pp.x + w1 * pp.y;
            }
            *(float4*)(g_imf + (size_t)b * CH * NP + (size_t)i * NP + j) =
                make_float4(vr[0], vr[1], vr[2], vr[3]);
        } else if constexpr (MODE == 2) {
            float w = g_wv[b * NP + i];
            #pragma unroll
            for (int c = 0; c < 4; c++) vr[c] *= w;
            *(float4*)(g_xcat + ((size_t)(b * NP + i)) * (2 * CH) + CH + j) =
                make_float4(vr[0], vr[1], vr[2], vr[3]);
        } else if constexpr (MODE == 3) {
            #pragma unroll
            for (int c = 0; c < 4; c++) vr[c] += p0[j + c];
            *(float4*)(g_x + ((size_t)(b * NP + i)) * CH + j) =
                make_float4(vr[0], vr[1], vr[2], vr[3]);
        } else if constexpr (MODE == 4) {
            #pragma unroll
            for (int c = 0; c < 4; c++) vr[c] = fmaxf(vr[c] + p0[j + c], 0.f);
            *(float4*)(g_h + ((size_t)(b * NP + i)) * FFNC + j) =
                make_float4(vr[0], vr[1], vr[2], vr[3]);
        } else {
            float4 res = *(const float4*)(g_x + ((size_t)(b * NP + i)) * CH + j);
            vr[0] += p0[j + 0] + res.x; vr[1] += p0[j + 1] + res.y;
            vr[2] += p0[j + 2] + res.z; vr[3] += p0[j + 3] + res.w;
            *(float4*)(g_y2 + ((size_t)(b * NP + i)) * CH + j) =
                make_float4(vr[0], vr[1], vr[2], vr[3]);
        }
    }
}

// ---------------- LayerNorm in place on g_x ----------------
__global__ void k_ln(const float* __restrict__ gamma, const float* __restrict__ beta) {
    int row = blockIdx.x * 8 + (threadIdx.x >> 5);
    int lane = threadIdx.x & 31;
    float* x = g_x + (size_t)row * CH + lane * 8;
    float4 v0 = *(float4*)x;
    float4 v1 = *(float4*)(x + 4);
    float s = v0.x + v0.y + v0.z + v0.w + v1.x + v1.y + v1.z + v1.w;
    float s2 = v0.x * v0.x + v0.y * v0.y + v0.z * v0.z + v0.w * v0.w +
               v1.x * v1.x + v1.y * v1.y + v1.z * v1.z + v1.w * v1.w;
    #pragma unroll
    for (int o = 16; o; o >>= 1) {
        s  += __shfl_xor_sync(0xffffffffu, s, o);
        s2 += __shfl_xor_sync(0xffffffffu, s2, o);
    }
    float mu = s * (1.f / CH);
    float var = s2 * (1.f / CH) - mu * mu;
    float inv = rsqrtf(var + 1e-5f);
    int c = lane * 8;
    float4 g0 = *(const float4*)(gamma + c), g1 = *(const float4*)(gamma + c + 4);
    float4 b0 = *(const float4*)(beta + c),  b1 = *(const float4*)(beta + c + 4);
    v0.x = (v0.x - mu) * inv * g0.x + b0.x; v0.y = (v0.y - mu) * inv * g0.y + b0.y;
    v0.z = (v0.z - mu) * inv * g0.z + b0.z; v0.w = (v0.w - mu) * inv * g0.w + b0.w;
    v1.x = (v1.x - mu) * inv * g1.x + b1.x; v1.y = (v1.y - mu) * inv * g1.y + b1.y;
    v1.z = (v1.z - mu) * inv * g1.z + b1.z; v1.w = (v1.w - mu) * inv * g1.w + b1.w;
    *(float4*)x = v0;
    *(float4*)(x + 4) = v1;
}

// ---------------- final LN + prediction head + outputs ----------------
__global__ void k_final(const float* __restrict__ gamma, const float* __restrict__ beta,
                        const float* __restrict__ Wpred, const float* __restrict__ bpred,
                        const float* __restrict__ ppos,
                        float* __restrict__ out_x, float* __restrict__ out_np,
                        float* __restrict__ out_c) {
    int row = blockIdx.x * 8 + (threadIdx.x >> 5);
    int lane = threadIdx.x & 31;
    int b = row >> 11, n = row & (NP - 1);
    const float* y = g_y2 + (size_t)row * CH + lane * 8;
    float4 v0 = *(const float4*)y;
    float4 v1 = *(const float4*)(y + 4);
    float s = v0.x + v0.y + v0.z + v0.w + v1.x + v1.y + v1.z + v1.w;
    float s2 = v0.x * v0.x + v0.y * v0.y + v0.z * v0.z + v0.w * v0.w +
               v1.x * v1.x + v1.y * v1.y + v1.z * v1.z + v1.w * v1.w;
    #pragma unroll
    for (int o = 16; o; o >>= 1) {
        s  += __shfl_xor_sync(0xffffffffu, s, o);
        s2 += __shfl_xor_sync(0xffffffffu, s2, o);
    }
    float mu = s * (1.f / CH);
    float var = s2 * (1.f / CH) - mu * mu;
    float inv = rsqrtf(var + 1e-5f);
    int c = lane * 8;
    float4 g0 = *(const float4*)(gamma + c), g1 = *(const float4*)(gamma + c + 4);
    float4 b0 = *(const float4*)(beta + c),  b1 = *(const float4*)(beta + c + 4);
    v0.x = (v0.x - mu) * inv * g0.x + b0.x; v0.y = (v0.y - mu) * inv * g0.y + b0.y;
    v0.z = (v0.z - mu) * inv * g0.z + b0.z; v0.w = (v0.w - mu) * inv * g0.w + b0.w;
    v1.x = (v1.x - mu) * inv * g1.x + b1.x; v1.y = (v1.y - mu) * inv * g1.y + b1.y;
    v1.z = (v1.z - mu) * inv * g1.z + b1.z; v1.w = (v1.w - mu) * inv * g1.w + b1.w;

    float4 w00 = *(const float4*)(Wpred + c),      w01 = *(const float4*)(Wpred + c + 4);
    float4 w10 = *(const float4*)(Wpred + CH + c), w11 = *(const float4*)(Wpred + CH + c + 4);
    float d0 = v0.x * w00.x + v0.y * w00.y + v0.z * w00.z + v0.w * w00.w +
               v1.x * w01.x + v1.y * w01.y + v1.z * w01.z + v1.w * w01.w;
    float d1 = v0.x * w10.x + v0.y * w10.y + v0.z * w10.z + v0.w * w10.w +
               v1.x * w11.x + v1.y * w11.y + v1.z * w11.z + v1.w * w11.w;
    #pragma unroll
    for (int o = 16; o; o >>= 1) {
        d0 += __shfl_xor_sync(0xffffffffu, d0, o);
        d1 += __shfl_xor_sync(0xffffffffu, d1, o);
    }
    float* ox = out_x + (size_t)b * CH * NP + n;
    ox[(size_t)(c + 0) * NP] = v0.x; ox[(size_t)(c + 1) * NP] = v0.y;
    ox[(size_t)(c + 2) * NP] = v0.z; ox[(size_t)(c + 3) * NP] = v0.w;
    ox[(size_t)(c + 4) * NP] = v1.x; ox[(size_t)(c + 5) * NP] = v1.y;
    ox[(size_t)(c + 6) * NP] = v1.z; ox[(size_t)(c + 7) * NP] = v1.w;
    if (lane == 0) {
        float2 pp = ((const float2*)ppos)[b * NP + n];
        float c0 = d0 + bpred[0] + pp.x;
        float c1 = d1 + bpred[1] + pp.y;
        out_c[(size_t)b * 2 * NP + n] = c0;
        out_c[(size_t)b * 2 * NP + NP + n] = c1;
        ((float2*)out_np)[b * NP + n] = make_float2(c0, c1);
    }
}

// ---------------- launch ----------------
extern "C" void kernel_launch(void* const* d_in, const int* in_sizes, int n_in,
                              void* d_out, int out_size) {
    const float* ptsf   = (const float*)d_in[0];
    const float* ppos   = (const float*)d_in[1];
    const float* imgf   = (const float*)d_in[2];
    const float* ipos   = (const float*)d_in[3];
    const float* ptscls = (const float*)d_in[4];
    const float* imgcls = (const float*)d_in[5];
    const float* Wp  = (const float*)d_in[6];  const float* bp  = (const float*)d_in[7];
    const float* Wi  = (const float*)d_in[8];  const float* bi  = (const float*)d_in[9];
    const float* Wqp = (const float*)d_in[10]; const float* bqp = (const float*)d_in[11];
    const float* Wkp = (const float*)d_in[12]; const float* bkp = (const float*)d_in[13];
    const float* Wout = (const float*)d_in[14]; const float* bout = (const float*)d_in[15];
    const float* gout = (const float*)d_in[16]; const float* betaout = (const float*)d_in[17];
    const float* Wf1 = (const float*)d_in[18]; const float* bf1 = (const float*)d_in[19];
    const float* Wf2 = (const float*)d_in[20]; const float* bf2 = (const float*)d_in[21];
    const float* gln = (const float*)d_in[22]; const float* bln = (const float*)d_in[23];
    const float* Wpred = (const float*)d_in[24]; const float* bpred = (const float*)d_in[25];

    float* out    = (float*)d_out;
    float* out_x  = out;                                   // [2,256,2048]
    float* out_np = out + (size_t)BSZ * CH * NP;           // [2,2048,2]
    float* out_c  = out_np + (size_t)BSZ * NP * 2;         // [2,2,2048]

    dim3 tb(32, 8);
    k_transpose<<<dim3(NP / 32, CH / 32, BSZ), tb>>>(ptsf, 0);
    k_transpose<<<dim3(NP / 32, CH / 32, BSZ), tb>>>(imgf, 1);
    k_cls<<<NROW / 256, 256>>>(ptscls, imgcls);
    k_cost<<<dim3(NP, BSZ), 256>>>(ppos, ipos);
    k_binit<<<NROW / 256, 256>>>();

    // projections + positional embeddings
    k_gemm<0><<<dim3(CH / 64, NP / 128, BSZ), 256>>>(Wp, bp, bqp, Wqp, ppos);
    k_gemm<1><<<dim3(NP / 64, CH / 128, BSZ), 256>>>(Wi, bi, bkp, Wkp, ipos);

    // IPOT iterations
    for (int t = 1; t <= 100; t++) {
        k_ipot_row<<<dim3(NP, BSZ), 256>>>(t);
        k_ipot_col<<<dim3(NP / 16, BSZ), 256>>>();
    }
    k_rownorm<<<dim3(NP, BSZ), 256>>>();

    // attention GEMM: img_att = res_norm @ imf^T  (scaled Q)
    k_gemm<2><<<dim3(CH / 64, NP / 128, BSZ), 256>>>(nullptr, nullptr, nullptr, nullptr, nullptr);
    // out projection + LN
    k_gemm<3><<<dim3(CH / 64, NP / 128, BSZ), 256>>>(Wout, bout, nullptr, nullptr, nullptr);
    k_ln<<<NROW / 8, 256>>>(gout, betaout);
    // FFN
    k_gemm<4><<<dim3(FFNC / 64, NP / 128, BSZ), 256>>>(Wf1, bf1, nullptr, nullptr, nullptr);
    k_gemm<5><<<dim3(CH / 64, NP / 128, BSZ), 256>>>(Wf2, bf2, nullptr, nullptr, nullptr);
    // final LN + head + outputs
    k_final<<<NROW / 8, 256>>>(gln, bln, Wpred, bpred, ppos, out_x, out_np, out_c);
}